// round 13
// baseline (speedup 1.0000x reference)
#include <cuda_runtime.h>
#include <cuda_fp16.h>
#include <math.h>
#include <stdint.h>

#define Bn   4
#define Cn   256
#define Sn   4096
#define DFFn 1024
#define NBn  128
#define NSPLIT 16

#define BSC (Bn*Sn*Cn)
#define BST (Bn*Sn*DFFn)

// ---- scratch ----
__device__ float g_X1[BSC];
__device__ float g_X2[BSC];
__device__ float g_ATT[BSC];
__device__ float g_H[BSC];
__device__ float g_T[BST];          // proj Yraw fp32, later T hi/lo u32 splits
__device__ float g_GO[Bn*NSPLIT*32*256];
__device__ float g_GM[Bn*NSPLIT*32];
__device__ float g_GL[Bn*NSPLIT*32];
// pre-split operand arrays (u32 = half2)
__device__ uint32_t g_WSH[32768],   g_WSL[32768];    // W  A-layout [256][128]
__device__ uint32_t g_W1SH[131072], g_W1SL[131072];  // w1 B-layout [128][1024]
__device__ uint32_t g_W2SH[131072], g_W2SL[131072];  // w2 B-layout [512][256]
__device__ uint32_t g_SBH[4194304], g_SBL[4194304];  // src B-layout [2][512][4096]
__device__ uint32_t g_HSH[2097152], g_HSL[2097152];  // H  A-layout [16384][128]

// ============================================================
// fp16-split helpers
// ============================================================
__device__ __forceinline__ void split2(float a, float b, uint32_t& h, uint32_t& l) {
    __half ha = __float2half_rn(a), hb = __float2half_rn(b);
    __half la = __float2half_rn(a - __half2float(ha));
    __half lb = __float2half_rn(b - __half2float(hb));
    __half2 hh = __halves2half2(ha, hb), ll = __halves2half2(la, lb);
    h = *reinterpret_cast<const uint32_t*>(&hh);
    l = *reinterpret_cast<const uint32_t*>(&ll);
}

#define MMA_F16(c, a, b0, b1) \
    asm volatile("mma.sync.aligned.m16n8k16.row.col.f32.f16.f16.f32 " \
        "{%0,%1,%2,%3}, {%4,%5,%6,%7}, {%8,%9}, {%0,%1,%2,%3};" \
        : "+f"((c)[0]), "+f"((c)[1]), "+f"((c)[2]), "+f"((c)[3]) \
        : "r"((a)[0]), "r"((a)[1]), "r"((a)[2]), "r"((a)[3]), "r"(b0), "r"(b1))

// ============================================================
// conversion kernels (one-shot pre-splits)
// ============================================================
// A-layout: pairs adjacent in k (contiguous): out[i] = split(in[2i], in[2i+1])
__global__ __launch_bounds__(256) void conv_a_kernel(
    const float* __restrict__ in, uint32_t* __restrict__ oh, uint32_t* __restrict__ ol)
{
    int i = blockIdx.x*256 + threadIdx.x;
    float2 v = reinterpret_cast<const float2*>(in)[i];
    split2(v.x, v.y, oh[i], ol[i]);
}
// B-layout: pairs across k-rows: out[kp*N+n] = split(in[2kp*N+n], in[(2kp+1)*N+n])
__global__ __launch_bounds__(256) void conv_b_kernel(
    const float* __restrict__ in, uint32_t* __restrict__ oh, uint32_t* __restrict__ ol,
    int N)
{
    int i = blockIdx.x*256 + threadIdx.x;
    int kp = i / N, n = i - kp*N;
    split2(in[2*kp*N + n], in[(2*kp+1)*N + n], oh[i], ol[i]);
}
// src B-layout (both srcs, N=4096, pairs over channel dim; C even so pairs
// never cross batches). grid (8192, 2)
__global__ __launch_bounds__(256) void conv_src_kernel(
    const float* __restrict__ s1, const float* __restrict__ s2,
    uint32_t* __restrict__ oh, uint32_t* __restrict__ ol)
{
    int i = blockIdx.x*256 + threadIdx.x;          // 0..2097151
    const float* in = blockIdx.y ? s2 : s1;
    int base = blockIdx.y * 2097152;
    int kp = i >> 12, s = i & 4095;
    split2(in[(kp << 13) + s], in[(kp << 13) + 4096 + s],
           oh[base + i], ol[base + i]);
}

// ============================================================
// pre-split fp16 (3-pass) mma GEMM: 128x128 tile, 256 thr.
// A: [m][K/2] u32, B: [K/2][N] u32 (both hi+lo), tile offsets pre-applied.
// ============================================================
#define AP 12
#define BP 136

__device__ __forceinline__ void f16_gemm_pre(
    const uint32_t* __restrict__ AHg, const uint32_t* __restrict__ ALg, int ldap,
    const uint32_t* __restrict__ BHg, const uint32_t* __restrict__ BLg, int ldb,
    int Ktot, uint32_t* AH, uint32_t* AL, uint32_t* BH, uint32_t* BL,
    float acc[2][8][4], int t)
{
    const int lane = t & 31, w = t >> 5;
    const int wm = w >> 1, wn = w & 1;
    const int q = lane & 3;
    const int am = t >> 1, ah4 = (t & 1) << 2;
    const int bkp = t >> 5, bn4 = lane << 2;
    const int KP2 = Ktot >> 1;

    uint4 pah, pal, pbh, pbl;
    pah = *reinterpret_cast<const uint4*>(AHg + am*ldap + ah4);
    pal = *reinterpret_cast<const uint4*>(ALg + am*ldap + ah4);
    pbh = *reinterpret_cast<const uint4*>(BHg + bkp*ldb + bn4);
    pbl = *reinterpret_cast<const uint4*>(BLg + bkp*ldb + bn4);

    for (int kp0 = 0; kp0 < KP2; kp0 += 8) {
        *reinterpret_cast<uint4*>(AH + am*AP + ah4) = pah;
        *reinterpret_cast<uint4*>(AL + am*AP + ah4) = pal;
        *reinterpret_cast<uint4*>(BH + bkp*BP + bn4) = pbh;
        *reinterpret_cast<uint4*>(BL + bkp*BP + bn4) = pbl;
        __syncthreads();

        if (kp0 + 8 < KP2) {
            pah = *reinterpret_cast<const uint4*>(AHg + am*ldap + kp0 + 8 + ah4);
            pal = *reinterpret_cast<const uint4*>(ALg + am*ldap + kp0 + 8 + ah4);
            pbh = *reinterpret_cast<const uint4*>(BHg + (kp0 + 8 + bkp)*ldb + bn4);
            pbl = *reinterpret_cast<const uint4*>(BLg + (kp0 + 8 + bkp)*ldb + bn4);
        }

        uint32_t Ah[2][4], Al[2][4];
#pragma unroll
        for (int mt = 0; mt < 2; mt++) {
            int r0 = (wm << 5) + (mt << 4) + (lane >> 2);
            Ah[mt][0] = AH[r0*AP + q];     Ah[mt][1] = AH[(r0+8)*AP + q];
            Ah[mt][2] = AH[r0*AP + q + 4]; Ah[mt][3] = AH[(r0+8)*AP + q + 4];
            Al[mt][0] = AL[r0*AP + q];     Al[mt][1] = AL[(r0+8)*AP + q];
            Al[mt][2] = AL[r0*AP + q + 4]; Al[mt][3] = AL[(r0+8)*AP + q + 4];
        }
#pragma unroll
        for (int nt = 0; nt < 8; nt++) {
            int nb = (wn << 6) + (nt << 3) + (lane >> 2);
            uint32_t bh0 = BH[q*BP + nb], bh1 = BH[(q+4)*BP + nb];
            uint32_t bl0 = BL[q*BP + nb], bl1 = BL[(q+4)*BP + nb];
#pragma unroll
            for (int mt = 0; mt < 2; mt++) {
                MMA_F16(acc[mt][nt], Ah[mt], bh0, bh1);
                MMA_F16(acc[mt][nt], Ah[mt], bl0, bl1);
                MMA_F16(acc[mt][nt], Al[mt], bh0, bh1);
            }
        }
        __syncthreads();
    }
}

#define GEMM_SM_DECL \
    __shared__ uint32_t AH[128*AP], AL[128*AP], BH[8*BP], BL[8*BP]

// ============================================================
// K1a: proj GEMM: Yraw[b][s][o] = sum_c W[o][c] src[b][c][s]
// grid (2, 32, 8=B*2), block 256.
// ============================================================
__global__ __launch_bounds__(256) void proj_gemm_kernel()
{
    GEMM_SM_DECL;
    const int z = blockIdx.z, b = z >> 1, ssel = z & 1;
    float* Yraw = g_T + ssel*BSC;
    const int m0 = blockIdx.x << 7;   // o
    const int n0 = blockIdx.y << 7;   // s
    const int t = threadIdx.x;
    const int lane = t & 31, w = t >> 5, wm = w >> 1, wn = w & 1;

    float acc[2][8][4];
#pragma unroll
    for (int a = 0; a < 2; a++)
#pragma unroll
        for (int b2_ = 0; b2_ < 8; b2_++)
#pragma unroll
            for (int c = 0; c < 4; c++) acc[a][b2_][c] = 0.f;

    const int sb = ssel*2097152 + b*(128*4096) + n0;
    f16_gemm_pre(g_WSH + m0*128, g_WSL + m0*128, 128,
                 g_SBH + sb, g_SBL + sb, 4096,
                 Cn, AH, AL, BH, BL, acc, t);

#pragma unroll
    for (int mt = 0; mt < 2; mt++)
#pragma unroll
    for (int i = 0; i < 2; i++) {
        int o = m0 + (wm << 5) + (mt << 4) + (lane >> 2) + (i << 3);
#pragma unroll
        for (int nt = 0; nt < 8; nt++) {
            int s = n0 + (wn << 6) + (nt << 3) + ((lane & 3) << 1);
            Yraw[(((b << 12) + s    ) << 8) + o] = acc[mt][nt][2*i];
            Yraw[(((b << 12) + s + 1) << 8) + o] = acc[mt][nt][2*i + 1];
        }
    }
}

// ============================================================
// K1b: LN over proj raw. warp per row.
// ============================================================
__global__ __launch_bounds__(256) void proj_ln_kernel(
    const float* __restrict__ bias, const float* __restrict__ gam,
    const float* __restrict__ bet)
{
    const int gr   = (blockIdx.x << 3) + (threadIdx.x >> 5);
    const int ssel = gr >= Bn*Sn;
    const int row  = ssel ? gr - Bn*Sn : gr;
    const float* Yraw = g_T + ssel*BSC;
    float* Xout       = ssel ? g_X2 : g_X1;
    const int lane = threadIdx.x & 31;
    const int base = row << 8;
    float v[8]; float sum = 0.f, sq = 0.f;
#pragma unroll
    for (int k = 0; k < 8; k++) {
        int o = lane + (k << 5);
        v[k] = Yraw[base + o] + bias[o];
        sum += v[k]; sq += v[k]*v[k];
    }
#pragma unroll
    for (int o = 16; o > 0; o >>= 1) {
        sum += __shfl_xor_sync(0xffffffffu, sum, o);
        sq  += __shfl_xor_sync(0xffffffffu, sq , o);
    }
    float mean = sum * (1.f/256.f);
    float var  = sq  * (1.f/256.f) - mean*mean;
    float rstd = rsqrtf(var + 1e-5f);
#pragma unroll
    for (int k = 0; k < 8; k++) {
        int o = lane + (k << 5);
        Xout[base + o] = (v[k] - mean)*rstd*gam[o] + bet[o];
    }
}

// ============================================================
// attention (unchanged R12 winner): score via split-fp16 mma
// ============================================================
#define QKP 132
#define VP4 260
#define SSP 36
#define ATTN_SMEM_FLOATS (4*32*QKP + 32*VP4 + 32*SSP + 96)

__device__ __forceinline__ void attn_tile(
    const float* __restrict__ X2, int b, int kb, int t,
    const uint32_t* Qhi, const uint32_t* Qlo,
    uint32_t* Khi, uint32_t* Klo,
    float* vsm, float* ssm,
    float* mrow, float* lrow, float* arow,
    float out0[16], float out1[16])
{
    const int tx = t & 15, ty = t >> 4;
    const int warp = t >> 5, lane = t & 31;
    const int c2 = t & 127, rh = (t >> 7) << 4;

#pragma unroll
    for (int i = 0; i < 16; i++) {
        int row = rh + i;
        float2 gl = *reinterpret_cast<const float2*>(
            X2 + (((b << 12) + (kb << 5) + row) << 8) + 2*c2);
        uint32_t h, l;
        split2(gl.x, gl.y, h, l);
        Khi[row*QKP + c2] = h;
        Klo[row*QKP + c2] = l;
        *reinterpret_cast<float2*>(vsm + row*VP4 + 2*c2) = gl;
    }
    __syncthreads();

    {
        const int mh = warp >> 2, ne = warp & 3;
        const int gr = lane >> 2, q = lane & 3;
        const int ar0 = (mh << 4) + gr;
        const int bn  = (ne << 3) + gr;
        float c[4] = {0.f, 0.f, 0.f, 0.f};
#pragma unroll
        for (int ks = 0; ks < 16; ks++) {
            int kp = (ks << 3) + q;
            uint32_t a[4], al[4];
            a[0]  = Qhi[ar0*QKP + kp];     a[1]  = Qhi[(ar0+8)*QKP + kp];
            a[2]  = Qhi[ar0*QKP + kp + 4]; a[3]  = Qhi[(ar0+8)*QKP + kp + 4];
            al[0] = Qlo[ar0*QKP + kp];     al[1] = Qlo[(ar0+8)*QKP + kp];
            al[2] = Qlo[ar0*QKP + kp + 4]; al[3] = Qlo[(ar0+8)*QKP + kp + 4];
            uint32_t bh0 = Khi[bn*QKP + kp], bh1 = Khi[bn*QKP + kp + 4];
            uint32_t bl0 = Klo[bn*QKP + kp], bl1 = Klo[bn*QKP + kp + 4];
            MMA_F16(c, a, bh0, bh1);
            MMA_F16(c, a, bl0, bl1);
            MMA_F16(c, al, bh0, bh1);
        }
        const float scl = 0.0625f;
        int r  = (mh << 4) + gr;
        int cc = (ne << 3) + (q << 1);
        *reinterpret_cast<float2*>(ssm + r*SSP + cc) =
            make_float2(c[0]*scl, c[1]*scl);
        *reinterpret_cast<float2*>(ssm + (r+8)*SSP + cc) =
            make_float2(c[2]*scl, c[3]*scl);
    }
    __syncthreads();

#pragma unroll
    for (int r = 0; r < 4; r++) {
        int row = (warp << 2) + r;
        float sv = ssm[row*SSP + lane];
        float mx = sv;
#pragma unroll
        for (int o = 16; o > 0; o >>= 1)
            mx = fmaxf(mx, __shfl_xor_sync(0xffffffffu, mx, o));
        float mold = mrow[row];
        float mnew = fmaxf(mold, mx);
        float p = __expf(sv - mnew);
        float ps = p;
#pragma unroll
        for (int o = 16; o > 0; o >>= 1)
            ps += __shfl_xor_sync(0xffffffffu, ps, o);
        if (lane == 0) {
            float a = __expf(mold - mnew);
            arow[row] = a;
            lrow[row] = lrow[row]*a + ps;
            mrow[row] = mnew;
        }
        ssm[row*SSP + lane] = p;
    }
    __syncthreads();

    float a0 = arow[2*ty], a1 = arow[2*ty+1];
#pragma unroll
    for (int j = 0; j < 16; j++) { out0[j] *= a0; out1[j] *= a1; }
    const float* p0r = ssm + (2*ty)*SSP;
    const float* p1r = ssm + (2*ty+1)*SSP;
#pragma unroll 4
    for (int k = 0; k < 32; k++) {
        float p0 = p0r[k], p1 = p1r[k];
        const float* vrow = vsm + k*VP4 + 4*tx;
#pragma unroll
        for (int g = 0; g < 4; g++) {
            float4 v = *reinterpret_cast<const float4*>(vrow + (g << 6));
            out0[g*4+0] += p0*v.x; out0[g*4+1] += p0*v.y;
            out0[g*4+2] += p0*v.z; out0[g*4+3] += p0*v.w;
            out1[g*4+0] += p1*v.x; out1[g*4+1] += p1*v.y;
            out1[g*4+2] += p1*v.z; out1[g*4+3] += p1*v.w;
        }
    }
    __syncthreads();
}

__global__ __launch_bounds__(256) void attn_kernel(
    const float* __restrict__ X1, const float* __restrict__ X2,
    const int* __restrict__ bidx, int K, float* __restrict__ ATT,
    float* __restrict__ GO, float* __restrict__ GM, float* __restrict__ GL)
{
    extern __shared__ float sm[];
    uint32_t* Qhi = reinterpret_cast<uint32_t*>(sm);
    uint32_t* Qlo = Qhi + 32*QKP;
    uint32_t* Khi = Qlo + 32*QKP;
    uint32_t* Klo = Khi + 32*QKP;
    float* vsm  = sm + 4*32*QKP;
    float* ssm  = vsm + 32*VP4;
    float* mrow = ssm + 32*SSP;
    float* lrow = mrow + 32;
    float* arow = lrow + 32;

    const int b = blockIdx.y, x = blockIdx.x;
    const int t = threadIdx.x;
    const int tx = t & 15, ty = t >> 4;
    const int c2 = t & 127, rh = (t >> 7) << 4;
    const bool sparse = (x < NBn - 1);
    const int n = sparse ? (x + 1) : 0;

#pragma unroll
    for (int i = 0; i < 16; i++) {
        int row = rh + i;
        float2 gl = *reinterpret_cast<const float2*>(
            X1 + (((b << 12) + (n << 5) + row) << 8) + 2*c2);
        uint32_t h, l;
        split2(gl.x, gl.y, h, l);
        Qhi[row*QKP + c2] = h;
        Qlo[row*QKP + c2] = l;
    }
    if (t < 32) { mrow[t] = -1e30f; lrow[t] = 0.f; }

    float out0[16], out1[16];
#pragma unroll
    for (int j = 0; j < 16; j++) { out0[j] = 0.f; out1[j] = 0.f; }
    __syncthreads();

    if (sparse) {
        for (int it = 0; it < K; it++) {
            int kb = bidx[(n - 1)*K + it];
            if (it > 0 && kb == 0) break;
            attn_tile(X2, b, kb, t, Qhi, Qlo, Khi, Klo, vsm, ssm,
                      mrow, lrow, arow, out0, out1);
        }
        const float l0 = 1.f / lrow[2*ty];
        const float l1 = 1.f / lrow[2*ty+1];
        const int base0 = (((b << 12) + (n << 5) + 2*ty) << 8) + 4*tx;
        const int base1 = base0 + 256;
#pragma unroll
        for (int g = 0; g < 4; g++) {
            *reinterpret_cast<float4*>(ATT + base0 + (g << 6)) =
                make_float4(out0[g*4+0]*l0, out0[g*4+1]*l0, out0[g*4+2]*l0, out0[g*4+3]*l0);
            *reinterpret_cast<float4*>(ATT + base1 + (g << 6)) =
                make_float4(out1[g*4+0]*l1, out1[g*4+1]*l1, out1[g*4+2]*l1, out1[g*4+3]*l1);
        }
    } else {
        const int split = x - (NBn - 1);
        for (int it = 0; it < NBn/NSPLIT; it++) {
            int kb = split*(NBn/NSPLIT) + it;
            attn_tile(X2, b, kb, t, Qhi, Qlo, Khi, Klo, vsm, ssm,
                      mrow, lrow, arow, out0, out1);
        }
        const int gi = (b*NSPLIT + split)*32;
        const int base0 = ((gi + 2*ty) << 8) + 4*tx;
        const int base1 = base0 + 256;
#pragma unroll
        for (int g = 0; g < 4; g++) {
            *reinterpret_cast<float4*>(GO + base0 + (g << 6)) =
                make_float4(out0[g*4+0], out0[g*4+1], out0[g*4+2], out0[g*4+3]);
            *reinterpret_cast<float4*>(GO + base1 + (g << 6)) =
                make_float4(out1[g*4+0], out1[g*4+1], out1[g*4+2], out1[g*4+3]);
        }
        if (t < 32) { GM[gi + t] = mrow[t]; GL[gi + t] = lrow[t]; }
    }
}

__global__ __launch_bounds__(256) void attn_global_combine(
    const float* __restrict__ GO, const float* __restrict__ GM,
    const float* __restrict__ GL, float* __restrict__ ATT)
{
    const int b = blockIdx.x, q = blockIdx.y, t = threadIdx.x;
    float ms[NSPLIT], ls[NSPLIT];
    float M = -1e30f;
#pragma unroll
    for (int i = 0; i < NSPLIT; i++) {
        ms[i] = GM[(b*NSPLIT + i)*32 + q];
        ls[i] = GL[(b*NSPLIT + i)*32 + q];
        M = fmaxf(M, ms[i]);
    }
    float L = 0.f, acc = 0.f;
#pragma unroll
    for (int i = 0; i < NSPLIT; i++) {
        float e = __expf(ms[i] - M);
        L   += ls[i] * e;
        acc += GO[(((b*NSPLIT + i)*32 + q) << 8) + t] * e;
    }
    ATT[(((b << 12) + q) << 8) + t] = acc / L;
}

// ============================================================
// K3: H = LN(X1 + ATT); also emits H split A-layout (pairs via shfl)
// ============================================================
__global__ __launch_bounds__(256) void add_ln_kernel(
    const float* __restrict__ X1, const float* __restrict__ ATT,
    const float* __restrict__ gam, const float* __restrict__ bet,
    float* __restrict__ H)
{
    const int row  = (blockIdx.x << 3) + (threadIdx.x >> 5);
    const int lane = threadIdx.x & 31;
    const int base = row << 8;
    float v[8]; float sum = 0.f, sq = 0.f;
#pragma unroll
    for (int k = 0; k < 8; k++) {
        int o = lane + (k << 5);
        v[k] = X1[base + o] + ATT[base + o];
        sum += v[k]; sq += v[k]*v[k];
    }
#pragma unroll
    for (int o = 16; o > 0; o >>= 1) {
        sum += __shfl_xor_sync(0xffffffffu, sum, o);
        sq  += __shfl_xor_sync(0xffffffffu, sq , o);
    }
    float mean = sum * (1.f/256.f);
    float var  = sq  * (1.f/256.f) - mean*mean;
    float rstd = rsqrtf(var + 1e-5f);
#pragma unroll
    for (int k = 0; k < 8; k++) {
        int o = lane + (k << 5);
        float hv = (v[k] - mean)*rstd*gam[o] + bet[o];
        H[base + o] = hv;
        float hn = __shfl_down_sync(0xffffffffu, hv, 1);
        if (!(lane & 1)) {
            uint32_t hh, ll;
            split2(hv, hn, hh, ll);
            int pi = (row << 7) + (lane >> 1) + (k << 4);
            g_HSH[pi] = hh; g_HSL[pi] = ll;
        }
    }
}

// ============================================================
// K4: ffn1: T(split) = gelu(H @ w1 + b1). grid (128, 8), 256 thr
// ============================================================
__global__ __launch_bounds__(256) void ffn1_kernel(
    const float* __restrict__ b1, uint32_t* __restrict__ THH,
    uint32_t* __restrict__ THL)
{
    GEMM_SM_DECL;
    const int m0 = blockIdx.x << 7, n0 = blockIdx.y << 7;
    const int t = threadIdx.x;
    const int lane = t & 31, w = t >> 5, wm = w >> 1, wn = w & 1;

    float acc[2][8][4];
#pragma unroll
    for (int a = 0; a < 2; a++)
#pragma unroll
        for (int b_ = 0; b_ < 8; b_++)
#pragma unroll
            for (int c = 0; c < 4; c++) acc[a][b_][c] = 0.f;

    f16_gemm_pre(g_HSH + m0*128, g_HSL + m0*128, 128,
                 g_W1SH + n0, g_W1SL + n0, DFFn,
                 Cn, AH, AL, BH, BL, acc, t);

#pragma unroll
    for (int mt = 0; mt < 2; mt++)
#pragma unroll
    for (int i = 0; i < 2; i++) {
        int m = m0 + (wm << 5) + (mt << 4) + (lane >> 2) + (i << 3);
#pragma unroll
        for (int nt = 0; nt < 8; nt++) {
            int n = n0 + (wn << 6) + (nt << 3) + ((lane & 3) << 1);
            float x0 = acc[mt][nt][2*i]   + b1[n];
            float x1 = acc[mt][nt][2*i+1] + b1[n+1];
            float g0 = 0.5f*x0*(1.f + erff(x0*0.70710678118654752f));
            float g1 = 0.5f*x1*(1.f + erff(x1*0.70710678118654752f));
            uint32_t hh, ll;
            split2(g0, g1, hh, ll);
            int pi = (m << 9) + (n >> 1);
            THH[pi] = hh; THL[pi] = ll;
        }
    }
}

// ============================================================
// K5: ffn2: Out(B,C,S) = transpose(H + T @ w2 + b2). grid (128, 2), 256 thr
// ============================================================
__global__ __launch_bounds__(256) void ffn2_kernel(
    const uint32_t* __restrict__ THH, const uint32_t* __restrict__ THL,
    const float* __restrict__ b2, const float* __restrict__ H,
    float* __restrict__ Out)
{
    GEMM_SM_DECL;
    const int m0 = blockIdx.x << 7, n0 = blockIdx.y << 7;
    const int t = threadIdx.x;
    const int lane = t & 31, w = t >> 5, wm = w >> 1, wn = w & 1;

    float acc[2][8][4];
#pragma unroll
    for (int a = 0; a < 2; a++)
#pragma unroll
        for (int b_ = 0; b_ < 8; b_++)
#pragma unroll
            for (int c = 0; c < 4; c++) acc[a][b_][c] = 0.f;

    f16_gemm_pre(THH + m0*512, THL + m0*512, 512,
                 g_W2SH + n0, g_W2SL + n0, Cn,
                 DFFn, AH, AL, BH, BL, acc, t);

#pragma unroll
    for (int mt = 0; mt < 2; mt++)
#pragma unroll
    for (int i = 0; i < 2; i++) {
        int m = m0 + (wm << 5) + (mt << 4) + (lane >> 2) + (i << 3);
        int b = m >> 12;
        int s = m & 4095;
#pragma unroll
        for (int nt = 0; nt < 8; nt++) {
            int n = n0 + (wn << 6) + (nt << 3) + ((lane & 3) << 1);
            float2 h2 = *reinterpret_cast<const float2*>(H + m*Cn + n);
            float v0 = acc[mt][nt][2*i]   + b2[n]   + h2.x;
            float v1 = acc[mt][nt][2*i+1] + b2[n+1] + h2.y;
            Out[(((b << 8) + n    ) << 12) + s] = v0;
            Out[(((b << 8) + n + 1) << 12) + s] = v1;
        }
    }
}

// ============================================================
extern "C" void kernel_launch(void* const* d_in, const int* in_sizes, int n_in,
                              void* d_out, int out_size)
{
    const float* src1  = (const float*)d_in[0];
    const float* src2  = (const float*)d_in[1];
    const float* wproj = (const float*)d_in[2];
    const float* bproj = (const float*)d_in[3];
    const float* g13   = (const float*)d_in[4];
    const float* be13  = (const float*)d_in[5];
    const float* g12   = (const float*)d_in[6];
    const float* be12  = (const float*)d_in[7];
    const float* w1    = (const float*)d_in[8];
    const float* b1    = (const float*)d_in[9];
    const float* w2    = (const float*)d_in[10];
    const float* b2    = (const float*)d_in[11];
    const int*   bidx  = (const int*)d_in[12];
    const int K = in_sizes[12] / (NBn - 1);
    float* out = (float*)d_out;

    float *X1, *X2, *ATT, *H, *T, *GO, *GM, *GL;
    uint32_t *WSH, *WSL, *W1SH, *W1SL, *W2SH, *W2SL, *SBH, *SBL;
    cudaGetSymbolAddress((void**)&X1,  g_X1);
    cudaGetSymbolAddress((void**)&X2,  g_X2);
    cudaGetSymbolAddress((void**)&ATT, g_ATT);
    cudaGetSymbolAddress((void**)&H,   g_H);
    cudaGetSymbolAddress((void**)&T,   g_T);
    cudaGetSymbolAddress((void**)&GO,  g_GO);
    cudaGetSymbolAddress((void**)&GM,  g_GM);
    cudaGetSymbolAddress((void**)&GL,  g_GL);
    cudaGetSymbolAddress((void**)&WSH, g_WSH);
    cudaGetSymbolAddress((void**)&WSL, g_WSL);
    cudaGetSymbolAddress((void**)&W1SH, g_W1SH);
    cudaGetSymbolAddress((void**)&W1SL, g_W1SL);
    cudaGetSymbolAddress((void**)&W2SH, g_W2SH);
    cudaGetSymbolAddress((void**)&W2SL, g_W2SL);
    cudaGetSymbolAddress((void**)&SBH, g_SBH);
    cudaGetSymbolAddress((void**)&SBL, g_SBL);
    uint32_t* THH = reinterpret_cast<uint32_t*>(T);
    uint32_t* THL = THH + 8388608;

    const int attn_smem = ATTN_SMEM_FLOATS * 4;   // 105,856 B -> 2 CTA/SM
    cudaFuncSetAttribute(attn_kernel, cudaFuncAttributeMaxDynamicSharedMemorySize, attn_smem);

    // one-shot operand pre-splits
    conv_a_kernel<<<128, 256>>>(wproj, WSH, WSL);                  // 32768
    conv_b_kernel<<<512, 256>>>(w1, W1SH, W1SL, DFFn);             // 131072
    conv_b_kernel<<<512, 256>>>(w2, W2SH, W2SL, Cn);               // 131072
    conv_src_kernel<<<dim3(8192, 2), 256>>>(src1, src2, SBH, SBL); // 2x2097152

    proj_gemm_kernel<<<dim3(2, 32, Bn*2), 256>>>();
    proj_ln_kernel<<<(2*Bn*Sn)/8, 256>>>(bproj, g13, be13);

    attn_kernel<<<dim3(NBn - 1 + NSPLIT, Bn), 256, attn_smem>>>(
        X1, X2, bidx, K, ATT, GO, GM, GL);
    attn_global_combine<<<dim3(Bn, 32), 256>>>(GO, GM, GL, ATT);

    add_ln_kernel<<<(Bn*Sn)/8, 256>>>(X1, ATT, g12, be12, H);

    ffn1_kernel<<<dim3((Bn*Sn)/128, DFFn/128), 256>>>(b1, THH, THL);
    ffn2_kernel<<<dim3((Bn*Sn)/128, Cn/128), 256>>>(THH, THL, b2, H, out);
}